// round 8
// baseline (speedup 1.0000x reference)
#include <cuda_runtime.h>
#include <cuda_bf16.h>
#include <cstdint>

#define NP    200
#define NVERT 6890
#define NJ    24
#define MDIM  20670   // NVERT*3
#define KC    287     // compact K (masked rows dropped)
#define KP    288     // K padded to 18 x 16
#define KS    296     // smem K stride (bf16) — +8 pad, conflict-free ldmatrix
#define MP    256     // M padded
#define NBT   162     // N tiles of 128
#define BTROWS (NBT*128)   // 20736
#define PBLK  324     // prepB blocks of 64 rows
#define PC    8       // poses per LBS block

__constant__ int c_PARENT[NJ] = {0,0,0,0,1,2,3,4,5,6,7,8,9,9,9,12,13,14,16,17,18,19,20,21};
__constant__ int c_LEN[NJ]    = {4,3,3,3,3,3,3,3,3,2,2,2,4,3,3,2,3,3,3,3,3,3,2,2};
__constant__ int c_NBR[NJ][4] = {
  {0,1,2,3},{0,1,4,0},{0,2,5,0},{0,3,6,0},{1,4,7,0},{2,5,8,0},{3,6,9,0},{4,7,10,0},
  {5,8,11,0},{6,9,0,0},{7,10,0,0},{8,11,0,0},{12,13,14,15},{12,13,16,0},{12,14,17,0},{12,15,0,0},
  {13,16,18,0},{14,17,19,0},{16,18,20,0},{17,19,21,0},{18,20,22,0},{19,21,23,0},{20,22,0,0},{21,23,0,0}};

// Scratch (static device globals; no runtime allocation)
__device__ __align__(16) __nv_bfloat16 g_QMbf[MP*KP];          // QM bf16, [m][k]
__device__ __align__(16) __nv_bfloat16 g_Bt[(size_t)BTROWS*KP];// B bf16, [n][k]
__device__ float g_Gp [NP*NJ*12];
__device__ float g_Wc [NVERT*NJ];
__device__ float g_Tp [NP*MDIM];
__device__ float g_acc[32];                    // 0:E_D 1:E_Wi 2:E_W 3:E_A 4..26:E_K[j]
__device__ int   g_rowjb[KP], g_rowgk[KP];     // compact-k -> (jb, global row)

__device__ __forceinline__ uint32_t smem_u32(const void* p) {
  uint32_t a;
  asm("{ .reg .u64 t; cvta.to.shared.u64 t, %1; cvt.u32.u64 %0, t; }" : "=r"(a) : "l"(p));
  return a;
}

// ---------------- init: accumulators + compact-row tables ----------------
__global__ void init_kernel() {
  if (threadIdx.x == 0) {
    int kc = 0;
    for (int jb = 0; jb < 23; ++jb) {
      int lim = 4*c_LEN[jb] + 1;
      for (int l = 0; l < lim; ++l) { g_rowjb[kc] = jb; g_rowgk[kc] = jb*17 + l; ++kc; }
    }
    for (; kc < KP; ++kc) { g_rowjb[kc] = 0; g_rowgk[kc] = 0; }
  }
  if (threadIdx.x < 32) g_acc[threadIdx.x] = 0.f;
}

// ---------------- per-pose: quats, QM bf16 rows, kinematic chain ----------------
__global__ void pose_kernel(const float* __restrict__ theta,
                            const float* __restrict__ Jin,
                            const float* __restrict__ beta2) {
  int p = blockIdx.x*blockDim.x + threadIdx.x;
  if (p >= MP) return;
  __nv_bfloat16* qrow = g_QMbf + p*KP;
  if (p >= NP) {
    for (int k = 0; k < KP; ++k) qrow[k] = __float2bfloat16(0.f);
    return;
  }
  const float* th = theta + p*72;
  const float* Jp = Jin + p*72;

  float q[NJ][4];
  float Rl[NJ][9];
  float tl[NJ][3];
  for (int k = 0; k < NJ; ++k) {
    float x = th[3*k], y = th[3*k+1], z = th[3*k+2];
    float s2 = x*x + y*y + z*z;
    float aq = sqrtf(fmaxf(s2, 1e-16f));
    float sh = sinf(0.5f*aq);
    float iq = 1.f/aq;
    q[k][0] = x*iq*sh; q[k][1] = y*iq*sh; q[k][2] = z*iq*sh;
    q[k][3] = cosf(0.5f*aq) - 1.f;
    float a = fmaxf(sqrtf(s2), 1e-8f);
    float ia = 1.f/a;
    float nx = x*ia, ny = y*ia, nz = z*ia;
    float c = cosf(a), s = sinf(a), t1 = 1.f - c;
    Rl[k][0] = c + t1*nx*nx;    Rl[k][1] = t1*nx*ny - s*nz; Rl[k][2] = t1*nx*nz + s*ny;
    Rl[k][3] = t1*nx*ny + s*nz; Rl[k][4] = c + t1*ny*ny;    Rl[k][5] = t1*ny*nz - s*nx;
    Rl[k][6] = t1*nx*nz - s*ny; Rl[k][7] = t1*ny*nz + s*nx; Rl[k][8] = c + t1*nz*nz;
    if (k == 0) { tl[k][0]=Jp[0]; tl[k][1]=Jp[1]; tl[k][2]=Jp[2]; }
    else {
      int par = c_PARENT[k];
      tl[k][0] = Jp[3*k]   - Jp[3*par];
      tl[k][1] = Jp[3*k+1] - Jp[3*par+1];
      tl[k][2] = Jp[3*k+2] - Jp[3*par+2];
    }
  }
  float Rw[NJ][9], tw[NJ][3];
  for (int i = 0; i < 9; ++i) Rw[0][i] = Rl[0][i];
  for (int i = 0; i < 3; ++i) tw[0][i] = tl[0][i];
  for (int k = 1; k < NJ; ++k) {
    int par = c_PARENT[k];
    for (int i = 0; i < 3; ++i) {
      for (int j = 0; j < 3; ++j) {
        Rw[k][i*3+j] = Rw[par][i*3+0]*Rl[k][0+j] + Rw[par][i*3+1]*Rl[k][3+j] + Rw[par][i*3+2]*Rl[k][6+j];
      }
      tw[k][i] = Rw[par][i*3+0]*tl[k][0] + Rw[par][i*3+1]*tl[k][1] + Rw[par][i*3+2]*tl[k][2] + tw[par][i];
    }
  }
  for (int k = 0; k < NJ; ++k) {
    float jx = Jp[3*k], jy = Jp[3*k+1], jz = Jp[3*k+2];
    for (int i = 0; i < 3; ++i) {
      float off = Rw[k][i*3]*jx + Rw[k][i*3+1]*jy + Rw[k][i*3+2]*jz;
      g_Gp[p*288 + k*12 + i*4 + 0] = Rw[k][i*3+0];
      g_Gp[p*288 + k*12 + i*4 + 1] = Rw[k][i*3+1];
      g_Gp[p*288 + k*12 + i*4 + 2] = Rw[k][i*3+2];
      g_Gp[p*288 + k*12 + i*4 + 3] = tw[k][i] - off;
    }
  }
  // compact qm row -> bf16 (masked l positions dropped entirely)
  float b2 = beta2[0];
  int kc = 0;
  for (int j = 0; j < 23; ++j) {
    int jj = j + 1;
    int lim  = 4*c_LEN[j] + 1;
    int bpos = 4*c_LEN[jj];
    for (int l = 0; l < lim; ++l) {
      float v = 0.f;
      if (l < 16) {
        int g = l >> 2, cc = l & 3;
        if (g < c_LEN[jj]) v = q[c_NBR[jj][g]][cc];
      }
      if (l == bpos) v += b2;
      qrow[kc++] = __float2bfloat16(v);
    }
  }
  for (; kc < KP; ++kc) qrow[kc] = __float2bfloat16(0.f);
}

// ---------------- weights: W_change, E_Wi, E_W, E_A ----------------
__global__ void w_kernel(const float* __restrict__ Wp, const float* __restrict__ Wi,
                         const float* __restrict__ A) {
  __shared__ float sb0[8], sb1[8], sb2[8];
  int n = blockIdx.x*blockDim.x + threadIdx.x;
  float ewi = 0.f, ew = 0.f, ea = 0.f;
  if (n < NVERT) {
    float w[NJ]; float s = 0.f;
    #pragma unroll
    for (int k = 0; k < NJ; ++k) { w[k] = fmaxf(Wp[n*NJ+k], 0.f); s += w[k]; }
    float inv = 1.f/(s + 1e-8f);
    #pragma unroll
    for (int k = 0; k < NJ; ++k) {
      float wc = w[k]*inv;
      g_Wc[n*NJ + k] = wc;
      float d = wc - Wi[n*NJ+k];
      ewi += d*d;
      ew  += fabsf(wc);
    }
    for (int j = 0; j < 23; ++j) ea += fabsf(A[j*NVERT + n]);
  }
  for (int o = 16; o > 0; o >>= 1) {
    ewi += __shfl_down_sync(0xffffffffu, ewi, o);
    ew  += __shfl_down_sync(0xffffffffu, ew,  o);
    ea  += __shfl_down_sync(0xffffffffu, ea,  o);
  }
  int lane = threadIdx.x & 31, wid = threadIdx.x >> 5;
  if (lane == 0) { sb0[wid]=ewi; sb1[wid]=ew; sb2[wid]=ea; }
  __syncthreads();
  if (wid == 0) {
    ewi = (lane < 8) ? sb0[lane] : 0.f;
    ew  = (lane < 8) ? sb1[lane] : 0.f;
    ea  = (lane < 8) ? sb2[lane] : 0.f;
    for (int o = 4; o > 0; o >>= 1) {
      ewi += __shfl_down_sync(0xffffffffu, ewi, o);
      ew  += __shfl_down_sync(0xffffffffu, ew,  o);
      ea  += __shfl_down_sync(0xffffffffu, ea,  o);
    }
    if (lane == 0) {
      atomicAdd(&g_acc[1], ewi);
      atomicAdd(&g_acc[2], ew);
      atomicAdd(&g_acc[3], ea);
    }
  }
}

// ---------------- prep B: Bt[n][k] = bf16(relu(A[jb,n/3]) * K[gk][n]), + E_K ----------------
__global__ void __launch_bounds__(256) prepB_kernel(const float* __restrict__ K,
                                                    const float* __restrict__ A) {
  __shared__ __nv_bfloat16 sB[64*KP];   // 36864 B
  __shared__ float s_ek[23];
  int tid = threadIdx.x;
  int tn = tid & 63, tk = tid >> 6;     // 64 n-lanes x 4 k-slices
  int n0 = blockIdx.x * 64;
  int n  = n0 + tn;
  bool valid = (n < MDIM);
  if (tid < 23) s_ek[tid] = 0.f;
  // zero-init this thread's k-slice (covers pad cols; main loop overwrites k<KC)
  for (int k = tk; k < KP; k += 4) sB[tn*KP + k] = __float2bfloat16(0.f);
  __syncthreads();
  int cur = -1; float acc = 0.f;
  for (int k = tk; k < KC; k += 4) {
    int jb = g_rowjb[k];
    float val = 0.f, aw = 0.f;
    if (valid) {
      val = K[(size_t)g_rowgk[k]*MDIM + n];
      aw  = fmaxf(A[jb*NVERT + n/3], 0.f);
    }
    if (jb != cur) {
      if (cur >= 0 && acc != 0.f) atomicAdd(&s_ek[cur], acc);
      cur = jb; acc = 0.f;
    }
    acc += val*val;
    sB[tn*KP + k] = __float2bfloat16(val*aw);
  }
  if (cur >= 0 && acc != 0.f) atomicAdd(&s_ek[cur], acc);
  __syncthreads();
  if (tid < 23) {
    float v = s_ek[tid];
    if (v != 0.f) atomicAdd(&g_acc[4 + tid], v);
  }
  // coalesced copy to gmem (same layout)
  const uint32_t* src = (const uint32_t*)sB;
  uint32_t* dst = (uint32_t*)(g_Bt + (size_t)n0*KP);
  for (int i = tid; i < 64*KP/2; i += 256) dst[i] = src[i];
}

// ---------------- tensor-core GEMM via mma.sync bf16 (valid on plain sm_103) ----
// CTA 256 thr = 8 warps (4m x 2n), warp tile 32x64, CTA tile 128x128, full K=288 in smem.
__global__ void __launch_bounds__(256) gemm_mma(const float* __restrict__ T) {
  extern __shared__ char smem[];
  char* sA = smem;                       // [128][KS] bf16 = 75776 B
  char* sB = smem + 128*KS*2;            // [128][KS] bf16 = 75776 B
  int tid = threadIdx.x;
  int m0 = blockIdx.y*128, n0 = blockIdx.x*128;

  // fill A tile (rows m0..m0+127), 16B chunks; row stride gmem 288 bf16 = 36 uint4
  {
    const uint4* Ag = (const uint4*)g_QMbf + (size_t)m0*36;
    for (int i = tid; i < 128*36; i += 256) {
      int r = i/36, c = i - r*36;
      uint4 v = Ag[(size_t)r*36 + c];
      *(uint4*)(sA + (r*KS + c*8)*2) = v;
    }
  }
  // fill B tile (rows n0..n0+127)
  {
    const uint4* Bg = (const uint4*)g_Bt + (size_t)n0*36;
    for (int i = tid; i < 128*36; i += 256) {
      int r = i/36, c = i - r*36;
      uint4 v = Bg[(size_t)r*36 + c];
      *(uint4*)(sB + (r*KS + c*8)*2) = v;
    }
  }
  __syncthreads();

  uint32_t sAu = smem_u32(sA), sBu = smem_u32(sB);
  int warp = tid >> 5, lane = tid & 31;
  int wm = (warp >> 1) * 32;   // 0,32,64,96
  int wn = (warp & 1) * 64;    // 0,64

  float acc[2][8][4];
  #pragma unroll
  for (int mi = 0; mi < 2; ++mi)
    #pragma unroll
    for (int ni = 0; ni < 8; ++ni)
      #pragma unroll
      for (int r = 0; r < 4; ++r) acc[mi][ni][r] = 0.f;

  // ldmatrix lane address components
  int la_row = wm + (lane & 7) + ((lane >> 3) & 1) * 8;
  int la_k8  = (lane >> 4) * 8;
  int lb_row = wn + (lane >> 4) * 8 + (lane & 7);
  int lb_k8  = ((lane >> 3) & 1) * 8;

  for (int ks = 0; ks < KP/16; ++ks) {
    int k0 = ks*16;
    uint32_t a[2][4];
    #pragma unroll
    for (int mi = 0; mi < 2; ++mi) {
      uint32_t ad = sAu + (uint32_t)(((la_row + mi*16)*KS + k0 + la_k8) * 2);
      asm volatile("ldmatrix.sync.aligned.m8n8.x4.shared.b16 {%0,%1,%2,%3}, [%4];"
        : "=r"(a[mi][0]), "=r"(a[mi][1]), "=r"(a[mi][2]), "=r"(a[mi][3]) : "r"(ad));
    }
    uint32_t b[8][2];
    #pragma unroll
    for (int bi = 0; bi < 4; ++bi) {
      uint32_t ad = sBu + (uint32_t)(((lb_row + bi*16)*KS + k0 + lb_k8) * 2);
      uint32_t r0, r1, r2, r3;
      asm volatile("ldmatrix.sync.aligned.m8n8.x4.shared.b16 {%0,%1,%2,%3}, [%4];"
        : "=r"(r0), "=r"(r1), "=r"(r2), "=r"(r3) : "r"(ad));
      b[2*bi][0] = r0; b[2*bi][1] = r1;
      b[2*bi+1][0] = r2; b[2*bi+1][1] = r3;
    }
    #pragma unroll
    for (int mi = 0; mi < 2; ++mi)
      #pragma unroll
      for (int ni = 0; ni < 8; ++ni) {
        asm volatile(
          "mma.sync.aligned.m16n8k16.row.col.f32.bf16.bf16.f32 "
          "{%0,%1,%2,%3}, {%4,%5,%6,%7}, {%8,%9}, {%0,%1,%2,%3};"
          : "+f"(acc[mi][ni][0]), "+f"(acc[mi][ni][1]),
            "+f"(acc[mi][ni][2]), "+f"(acc[mi][ni][3])
          : "r"(a[mi][0]), "r"(a[mi][1]), "r"(a[mi][2]), "r"(a[mi][3]),
            "r"(b[ni][0]), "r"(b[ni][1]));
      }
  }

  // epilogue: += T, store to g_Tp
  int rbase = lane >> 2, cbase = (lane & 3) * 2;
  #pragma unroll
  for (int mi = 0; mi < 2; ++mi) {
    #pragma unroll
    for (int ni = 0; ni < 8; ++ni) {
      int row = m0 + wm + mi*16 + rbase;
      int col = n0 + wn + ni*8 + cbase;
      if (col + 1 < MDIM) {
        if (row < NP) {
          size_t o = (size_t)row*MDIM + col;
          float2 t = *(const float2*)(T + o);
          float2 w; w.x = acc[mi][ni][0] + t.x; w.y = acc[mi][ni][1] + t.y;
          *(float2*)(g_Tp + o) = w;
        }
        int row2 = row + 8;
        if (row2 < NP) {
          size_t o = (size_t)row2*MDIM + col;
          float2 t = *(const float2*)(T + o);
          float2 w; w.x = acc[mi][ni][2] + t.x; w.y = acc[mi][ni][3] + t.y;
          *(float2*)(g_Tp + o) = w;
        }
      }
    }
  }
}

// ---------------- LBS blend + verts + E_D ----------------
__global__ void __launch_bounds__(128) lbs_kernel(const float* __restrict__ V,
                                                  float* __restrict__ verts) {
  __shared__ __align__(16) float Gs[PC*288];
  __shared__ float sb[4];
  int tid = threadIdx.x;
  int p0 = blockIdx.y*PC;
  for (int i = tid; i < PC*288; i += 128) Gs[i] = g_Gp[p0*288 + i];
  __syncthreads();
  int n = blockIdx.x*128 + tid;
  float w[NJ];
  bool ok = (n < NVERT);
  if (ok) {
    const float4* wp = reinterpret_cast<const float4*>(&g_Wc[n*NJ]);
    #pragma unroll
    for (int k4 = 0; k4 < 6; ++k4) {
      float4 v = wp[k4];
      w[4*k4] = v.x; w[4*k4+1] = v.y; w[4*k4+2] = v.z; w[4*k4+3] = v.w;
    }
  }
  float ed = 0.f;
  #pragma unroll
  for (int pp = 0; pp < PC; ++pp) {
    if (!ok) break;
    int p = p0 + pp;
    float4 M0 = make_float4(0.f,0.f,0.f,0.f);
    float4 M1 = M0, M2 = M0;
    const float4* Gp4 = reinterpret_cast<const float4*>(&Gs[pp*288]);
    #pragma unroll
    for (int k = 0; k < NJ; ++k) {
      float wk = w[k];
      float4 g0 = Gp4[k*3+0], g1 = Gp4[k*3+1], g2 = Gp4[k*3+2];
      M0.x += wk*g0.x; M0.y += wk*g0.y; M0.z += wk*g0.z; M0.w += wk*g0.w;
      M1.x += wk*g1.x; M1.y += wk*g1.y; M1.z += wk*g1.z; M1.w += wk*g1.w;
      M2.x += wk*g2.x; M2.y += wk*g2.y; M2.z += wk*g2.z; M2.w += wk*g2.w;
    }
    size_t base = (size_t)p*MDIM + 3*n;
    float t0 = g_Tp[base], t1 = g_Tp[base+1], t2 = g_Tp[base+2];
    float vx = M0.x*t0 + M0.y*t1 + M0.z*t2 + M0.w;
    float vy = M1.x*t0 + M1.y*t1 + M1.z*t2 + M1.w;
    float vz = M2.x*t0 + M2.y*t1 + M2.z*t2 + M2.w;
    verts[base]   = vx;
    verts[base+1] = vy;
    verts[base+2] = vz;
    float dx = V[base]-vx, dy = V[base+1]-vy, dz = V[base+2]-vz;
    ed += dx*dx + dy*dy + dz*dz;
  }
  for (int o = 16; o > 0; o >>= 1) ed += __shfl_down_sync(0xffffffffu, ed, o);
  int lane = tid & 31, wd = tid >> 5;
  if (lane == 0) sb[wd] = ed;
  __syncthreads();
  if (tid == 0) atomicAdd(&g_acc[0], sb[0] + sb[1] + sb[2] + sb[3]);
}

// ---------------- E assembly ----------------
__global__ void finalize_kernel(const int* __restrict__ epoch_ptr, int has_epoch,
                                float* __restrict__ outE) {
  float e = has_epoch ? (float)epoch_ptr[0] : 1.f;
  float g_wi = 0.1f  *expf(-0.1f  *e);
  float g_w  = 0.002f*expf(-0.008f*e);
  float g_a  = 0.001f*expf(-0.008f*e);
  float g_k  = 0.1f  *expf(-0.008f*e);
  float ek = 0.f;
  for (int j = 0; j < 23; ++j) ek += sqrtf(g_acc[4+j]);
  outE[0] = g_acc[0] + g_wi*g_acc[1] + g_w*g_acc[2] + g_a*g_acc[3] + g_k*ek;
}

extern "C" void kernel_launch(void* const* d_in, const int* in_sizes, int n_in,
                              void* d_out, int out_size) {
  const float* V  = (const float*)d_in[0];
  const float* T  = (const float*)d_in[1];
  const float* J  = (const float*)d_in[2];
  const float* th = (const float*)d_in[3];
  const float* Wp = (const float*)d_in[4];
  const float* Wi = (const float*)d_in[5];
  const float* A  = (const float*)d_in[6];
  const float* K  = (const float*)d_in[7];
  const float* b2 = (const float*)d_in[8];
  const int*   ep = (n_in > 9) ? (const int*)d_in[9] : nullptr;

  float* out = (float*)d_out;
  int off = out_size - NP*MDIM;
  if (off < 0) off = 0;
  float* verts = out + off;

  const int GEMM_SMEM = 2*128*KS*2;  // 151552
  cudaFuncSetAttribute(gemm_mma, cudaFuncAttributeMaxDynamicSharedMemorySize, GEMM_SMEM);

  init_kernel<<<1, 32>>>();
  pose_kernel<<<4, 64>>>(th, J, b2);
  w_kernel<<<(NVERT + 255)/256, 256>>>(Wp, Wi, A);
  prepB_kernel<<<PBLK, 256>>>(K, A);
  gemm_mma<<<dim3(NBT, 2), 256, GEMM_SMEM>>>(T);
  lbs_kernel<<<dim3((NVERT + 127)/128, NP/PC), 128>>>(V, verts);
  if (off > 0) finalize_kernel<<<1, 1>>>(ep, ep != nullptr ? 1 : 0, out);
}

// round 9
// speedup vs baseline: 1.0949x; 1.0949x over previous
#include <cuda_runtime.h>
#include <cuda_bf16.h>
#include <cstdint>

#define NP    200
#define NVERT 6890
#define NJ    24
#define MDIM  20670   // NVERT*3
#define KC    287     // compact K (masked rows dropped)
#define KP    288     // K padded to 18 x 16
#define KS    296     // smem K stride (bf16) — +8 pad, conflict-free ldmatrix
#define MP    256     // M padded
#define NBT   162     // N tiles of 128
#define BTROWS (NBT*128)   // 20736
#define PBLK  324     // prepB blocks of 64 rows
#define PSTR  289     // prepB smem row stride (fp32 words, odd -> conflict-free)
#define PC    8       // poses per LBS block

__constant__ int c_PARENT[NJ] = {0,0,0,0,1,2,3,4,5,6,7,8,9,9,9,12,13,14,16,17,18,19,20,21};
__constant__ int c_LEN[NJ]    = {4,3,3,3,3,3,3,3,3,2,2,2,4,3,3,2,3,3,3,3,3,3,2,2};
__constant__ int c_NBR[NJ][4] = {
  {0,1,2,3},{0,1,4,0},{0,2,5,0},{0,3,6,0},{1,4,7,0},{2,5,8,0},{3,6,9,0},{4,7,10,0},
  {5,8,11,0},{6,9,0,0},{7,10,0,0},{8,11,0,0},{12,13,14,15},{12,13,16,0},{12,14,17,0},{12,15,0,0},
  {13,16,18,0},{14,17,19,0},{16,18,20,0},{17,19,21,0},{18,20,22,0},{19,21,23,0},{20,22,0,0},{21,23,0,0}};

// Scratch (static device globals; no runtime allocation)
__device__ __align__(16) __nv_bfloat16 g_QMbf[MP*KP];          // QM bf16, [m][k]
__device__ __align__(16) __nv_bfloat16 g_Bt[(size_t)BTROWS*KP];// B bf16, [n][k]
__device__ float g_Gp [NP*NJ*12];
__device__ float g_Wc [NVERT*NJ];
__device__ float g_Tp [NP*MDIM];
__device__ float g_acc[32];                    // 0:E_D 1:E_Wi 2:E_W 3:E_A 4..26:E_K[j]
__device__ int   g_rowjb[KP], g_rowgk[KP];     // compact-k -> (jb, global row)

__device__ __forceinline__ uint32_t smem_u32(const void* p) {
  uint32_t a;
  asm("{ .reg .u64 t; cvta.to.shared.u64 t, %1; cvt.u32.u64 %0, t; }" : "=r"(a) : "l"(p));
  return a;
}

// ---------------- init: accumulators + compact-row tables ----------------
__global__ void init_kernel() {
  if (threadIdx.x == 0) {
    int kc = 0;
    for (int jb = 0; jb < 23; ++jb) {
      int lim = 4*c_LEN[jb] + 1;
      for (int l = 0; l < lim; ++l) { g_rowjb[kc] = jb; g_rowgk[kc] = jb*17 + l; ++kc; }
    }
    for (; kc < KP; ++kc) { g_rowjb[kc] = 0; g_rowgk[kc] = 0; }
  }
  if (threadIdx.x < 32) g_acc[threadIdx.x] = 0.f;
}

// ---------------- per-pose: quats, QM bf16 rows, kinematic chain ----------------
__global__ void pose_kernel(const float* __restrict__ theta,
                            const float* __restrict__ Jin,
                            const float* __restrict__ beta2) {
  int p = blockIdx.x*blockDim.x + threadIdx.x;
  if (p >= MP) return;
  __nv_bfloat16* qrow = g_QMbf + p*KP;
  if (p >= NP) {
    for (int k = 0; k < KP; ++k) qrow[k] = __float2bfloat16(0.f);
    return;
  }
  const float* th = theta + p*72;
  const float* Jp = Jin + p*72;

  float q[NJ][4];
  float Rl[NJ][9];
  float tl[NJ][3];
  for (int k = 0; k < NJ; ++k) {
    float x = th[3*k], y = th[3*k+1], z = th[3*k+2];
    float s2 = x*x + y*y + z*z;
    float aq = sqrtf(fmaxf(s2, 1e-16f));
    float sh = sinf(0.5f*aq);
    float iq = 1.f/aq;
    q[k][0] = x*iq*sh; q[k][1] = y*iq*sh; q[k][2] = z*iq*sh;
    q[k][3] = cosf(0.5f*aq) - 1.f;
    float a = fmaxf(sqrtf(s2), 1e-8f);
    float ia = 1.f/a;
    float nx = x*ia, ny = y*ia, nz = z*ia;
    float c = cosf(a), s = sinf(a), t1 = 1.f - c;
    Rl[k][0] = c + t1*nx*nx;    Rl[k][1] = t1*nx*ny - s*nz; Rl[k][2] = t1*nx*nz + s*ny;
    Rl[k][3] = t1*nx*ny + s*nz; Rl[k][4] = c + t1*ny*ny;    Rl[k][5] = t1*ny*nz - s*nx;
    Rl[k][6] = t1*nx*nz - s*ny; Rl[k][7] = t1*ny*nz + s*nx; Rl[k][8] = c + t1*nz*nz;
    if (k == 0) { tl[k][0]=Jp[0]; tl[k][1]=Jp[1]; tl[k][2]=Jp[2]; }
    else {
      int par = c_PARENT[k];
      tl[k][0] = Jp[3*k]   - Jp[3*par];
      tl[k][1] = Jp[3*k+1] - Jp[3*par+1];
      tl[k][2] = Jp[3*k+2] - Jp[3*par+2];
    }
  }
  float Rw[NJ][9], tw[NJ][3];
  for (int i = 0; i < 9; ++i) Rw[0][i] = Rl[0][i];
  for (int i = 0; i < 3; ++i) tw[0][i] = tl[0][i];
  for (int k = 1; k < NJ; ++k) {
    int par = c_PARENT[k];
    for (int i = 0; i < 3; ++i) {
      for (int j = 0; j < 3; ++j) {
        Rw[k][i*3+j] = Rw[par][i*3+0]*Rl[k][0+j] + Rw[par][i*3+1]*Rl[k][3+j] + Rw[par][i*3+2]*Rl[k][6+j];
      }
      tw[k][i] = Rw[par][i*3+0]*tl[k][0] + Rw[par][i*3+1]*tl[k][1] + Rw[par][i*3+2]*tl[k][2] + tw[par][i];
    }
  }
  for (int k = 0; k < NJ; ++k) {
    float jx = Jp[3*k], jy = Jp[3*k+1], jz = Jp[3*k+2];
    for (int i = 0; i < 3; ++i) {
      float off = Rw[k][i*3]*jx + Rw[k][i*3+1]*jy + Rw[k][i*3+2]*jz;
      g_Gp[p*288 + k*12 + i*4 + 0] = Rw[k][i*3+0];
      g_Gp[p*288 + k*12 + i*4 + 1] = Rw[k][i*3+1];
      g_Gp[p*288 + k*12 + i*4 + 2] = Rw[k][i*3+2];
      g_Gp[p*288 + k*12 + i*4 + 3] = tw[k][i] - off;
    }
  }
  // compact qm row -> bf16 (masked l positions dropped entirely)
  float b2 = beta2[0];
  int kc = 0;
  for (int j = 0; j < 23; ++j) {
    int jj = j + 1;
    int lim  = 4*c_LEN[j] + 1;
    int bpos = 4*c_LEN[jj];
    for (int l = 0; l < lim; ++l) {
      float v = 0.f;
      if (l < 16) {
        int g = l >> 2, cc = l & 3;
        if (g < c_LEN[jj]) v = q[c_NBR[jj][g]][cc];
      }
      if (l == bpos) v += b2;
      qrow[kc++] = __float2bfloat16(v);
    }
  }
  for (; kc < KP; ++kc) qrow[kc] = __float2bfloat16(0.f);
}

// ---------------- weights: W_change, E_Wi, E_W, E_A ----------------
__global__ void w_kernel(const float* __restrict__ Wp, const float* __restrict__ Wi,
                         const float* __restrict__ A) {
  __shared__ float sb0[8], sb1[8], sb2[8];
  int n = blockIdx.x*blockDim.x + threadIdx.x;
  float ewi = 0.f, ew = 0.f, ea = 0.f;
  if (n < NVERT) {
    float w[NJ]; float s = 0.f;
    #pragma unroll
    for (int k = 0; k < NJ; ++k) { w[k] = fmaxf(Wp[n*NJ+k], 0.f); s += w[k]; }
    float inv = 1.f/(s + 1e-8f);
    #pragma unroll
    for (int k = 0; k < NJ; ++k) {
      float wc = w[k]*inv;
      g_Wc[n*NJ + k] = wc;
      float d = wc - Wi[n*NJ+k];
      ewi += d*d;
      ew  += fabsf(wc);
    }
    for (int j = 0; j < 23; ++j) ea += fabsf(A[j*NVERT + n]);
  }
  for (int o = 16; o > 0; o >>= 1) {
    ewi += __shfl_down_sync(0xffffffffu, ewi, o);
    ew  += __shfl_down_sync(0xffffffffu, ew,  o);
    ea  += __shfl_down_sync(0xffffffffu, ea,  o);
  }
  int lane = threadIdx.x & 31, wid = threadIdx.x >> 5;
  if (lane == 0) { sb0[wid]=ewi; sb1[wid]=ew; sb2[wid]=ea; }
  __syncthreads();
  if (wid == 0) {
    ewi = (lane < 8) ? sb0[lane] : 0.f;
    ew  = (lane < 8) ? sb1[lane] : 0.f;
    ea  = (lane < 8) ? sb2[lane] : 0.f;
    for (int o = 4; o > 0; o >>= 1) {
      ewi += __shfl_down_sync(0xffffffffu, ewi, o);
      ew  += __shfl_down_sync(0xffffffffu, ew,  o);
      ea  += __shfl_down_sync(0xffffffffu, ea,  o);
    }
    if (lane == 0) {
      atomicAdd(&g_acc[1], ewi);
      atomicAdd(&g_acc[2], ew);
      atomicAdd(&g_acc[3], ea);
    }
  }
}

// ---------------- prep B: Bt[n][k] = bf16(relu(A[jb,n/3]) * K[gk][n]), + E_K ----
// Padded fp32 smem transpose: row stride 289 words (odd) -> conflict-free STS.
__global__ void __launch_bounds__(256) prepB_kernel(const float* __restrict__ K,
                                                    const float* __restrict__ A) {
  extern __shared__ float s[];          // [64][PSTR] fp32 = 73984 B
  __shared__ float s_ek[23];
  __shared__ int s_jb[KP], s_gk[KP];
  int tid = threadIdx.x;
  if (tid < 23) s_ek[tid] = 0.f;
  for (int i = tid; i < KP; i += 256) { s_jb[i] = g_rowjb[i]; s_gk[i] = g_rowgk[i]; }
  __syncthreads();
  int tn = tid & 63, tk = tid >> 6;     // 64 n-lanes x 4 k-slices
  int n0 = blockIdx.x * 64;
  int n  = n0 + tn;
  bool valid = (n < MDIM);
  const float* Acol = A + (valid ? n/3 : 0);
  float* srow = s + tn*PSTR;
  if (tk == 0) srow[KC] = 0.f;          // single pad column k=287
  int cur = -1; float acc = 0.f;
  #pragma unroll 4
  for (int k = tk; k < KC; k += 4) {
    int jb = s_jb[k];
    float val = 0.f, aw = 0.f;
    if (valid) {
      val = __ldg(&K[(size_t)s_gk[k]*MDIM + n]);
      aw  = fmaxf(__ldg(&Acol[jb*NVERT]), 0.f);
    }
    if (jb != cur) {
      if (cur >= 0 && acc != 0.f) atomicAdd(&s_ek[cur], acc);
      cur = jb; acc = 0.f;
    }
    acc += val*val;
    srow[k] = val*aw;                   // bank = (tn + k) & 31 -> conflict-free
  }
  if (cur >= 0 && acc != 0.f) atomicAdd(&s_ek[cur], acc);
  __syncthreads();
  if (tid < 23) {
    float v = s_ek[tid];
    if (v != 0.f) atomicAdd(&g_acc[4 + tid], v);
  }
  // pack fp32 pairs -> bf16x2 words, coalesced gmem write
  uint32_t* dst = (uint32_t*)(g_Bt + (size_t)n0*KP);
  for (int i = tid; i < 64*(KP/2); i += 256) {
    int r = i/(KP/2), w = i - r*(KP/2);
    float lo = s[r*PSTR + 2*w], hi = s[r*PSTR + 2*w + 1];
    __nv_bfloat162 h2 = __floats2bfloat162_rn(lo, hi);
    dst[i] = *(uint32_t*)&h2;
  }
}

// ---------------- tensor-core GEMM via mma.sync bf16 (valid on plain sm_103) ----
// CTA 256 thr = 8 warps (4m x 2n), warp tile 32x64, CTA tile 128x128, full K=288 in smem.
__global__ void __launch_bounds__(256) gemm_mma(const float* __restrict__ T) {
  extern __shared__ char smem[];
  char* sA = smem;                       // [128][KS] bf16 = 75776 B
  char* sB = smem + 128*KS*2;            // [128][KS] bf16 = 75776 B
  int tid = threadIdx.x;
  int m0 = blockIdx.y*128, n0 = blockIdx.x*128;

  // fill A tile (rows m0..m0+127), 16B chunks; row stride gmem 288 bf16 = 36 uint4
  {
    const uint4* Ag = (const uint4*)g_QMbf + (size_t)m0*36;
    for (int i = tid; i < 128*36; i += 256) {
      int r = i/36, c = i - r*36;
      uint4 v = Ag[(size_t)r*36 + c];
      *(uint4*)(sA + (r*KS + c*8)*2) = v;
    }
  }
  // fill B tile (rows n0..n0+127)
  {
    const uint4* Bg = (const uint4*)g_Bt + (size_t)n0*36;
    for (int i = tid; i < 128*36; i += 256) {
      int r = i/36, c = i - r*36;
      uint4 v = Bg[(size_t)r*36 + c];
      *(uint4*)(sB + (r*KS + c*8)*2) = v;
    }
  }
  __syncthreads();

  uint32_t sAu = smem_u32(sA), sBu = smem_u32(sB);
  int warp = tid >> 5, lane = tid & 31;
  int wm = (warp >> 1) * 32;   // 0,32,64,96
  int wn = (warp & 1) * 64;    // 0,64

  float acc[2][8][4];
  #pragma unroll
  for (int mi = 0; mi < 2; ++mi)
    #pragma unroll
    for (int ni = 0; ni < 8; ++ni)
      #pragma unroll
      for (int r = 0; r < 4; ++r) acc[mi][ni][r] = 0.f;

  // ldmatrix lane address components
  int la_row = wm + (lane & 7) + ((lane >> 3) & 1) * 8;
  int la_k8  = (lane >> 4) * 8;
  int lb_row = wn + (lane >> 4) * 8 + (lane & 7);
  int lb_k8  = ((lane >> 3) & 1) * 8;

  for (int ks = 0; ks < KP/16; ++ks) {
    int k0 = ks*16;
    uint32_t a[2][4];
    #pragma unroll
    for (int mi = 0; mi < 2; ++mi) {
      uint32_t ad = sAu + (uint32_t)(((la_row + mi*16)*KS + k0 + la_k8) * 2);
      asm volatile("ldmatrix.sync.aligned.m8n8.x4.shared.b16 {%0,%1,%2,%3}, [%4];"
        : "=r"(a[mi][0]), "=r"(a[mi][1]), "=r"(a[mi][2]), "=r"(a[mi][3]) : "r"(ad));
    }
    uint32_t b[8][2];
    #pragma unroll
    for (int bi = 0; bi < 4; ++bi) {
      uint32_t ad = sBu + (uint32_t)(((lb_row + bi*16)*KS + k0 + lb_k8) * 2);
      uint32_t r0, r1, r2, r3;
      asm volatile("ldmatrix.sync.aligned.m8n8.x4.shared.b16 {%0,%1,%2,%3}, [%4];"
        : "=r"(r0), "=r"(r1), "=r"(r2), "=r"(r3) : "r"(ad));
      b[2*bi][0] = r0; b[2*bi][1] = r1;
      b[2*bi+1][0] = r2; b[2*bi+1][1] = r3;
    }
    #pragma unroll
    for (int mi = 0; mi < 2; ++mi)
      #pragma unroll
      for (int ni = 0; ni < 8; ++ni) {
        asm volatile(
          "mma.sync.aligned.m16n8k16.row.col.f32.bf16.bf16.f32 "
          "{%0,%1,%2,%3}, {%4,%5,%6,%7}, {%8,%9}, {%0,%1,%2,%3};"
          : "+f"(acc[mi][ni][0]), "+f"(acc[mi][ni][1]),
            "+f"(acc[mi][ni][2]), "+f"(acc[mi][ni][3])
          : "r"(a[mi][0]), "r"(a[mi][1]), "r"(a[mi][2]), "r"(a[mi][3]),
            "r"(b[ni][0]), "r"(b[ni][1]));
      }
  }

  // epilogue: += T, store to g_Tp
  int rbase = lane >> 2, cbase = (lane & 3) * 2;
  #pragma unroll
  for (int mi = 0; mi < 2; ++mi) {
    #pragma unroll
    for (int ni = 0; ni < 8; ++ni) {
      int row = m0 + wm + mi*16 + rbase;
      int col = n0 + wn + ni*8 + cbase;
      if (col + 1 < MDIM) {
        if (row < NP) {
          size_t o = (size_t)row*MDIM + col;
          float2 t = *(const float2*)(T + o);
          float2 w; w.x = acc[mi][ni][0] + t.x; w.y = acc[mi][ni][1] + t.y;
          *(float2*)(g_Tp + o) = w;
        }
        int row2 = row + 8;
        if (row2 < NP) {
          size_t o = (size_t)row2*MDIM + col;
          float2 t = *(const float2*)(T + o);
          float2 w; w.x = acc[mi][ni][2] + t.x; w.y = acc[mi][ni][3] + t.y;
          *(float2*)(g_Tp + o) = w;
        }
      }
    }
  }
}

// ---------------- LBS blend + verts + E_D ----------------
__global__ void __launch_bounds__(128) lbs_kernel(const float* __restrict__ V,
                                                  float* __restrict__ verts) {
  __shared__ __align__(16) float Gs[PC*288];
  __shared__ float sb[4];
  int tid = threadIdx.x;
  int p0 = blockIdx.y*PC;
  for (int i = tid; i < PC*288; i += 128) Gs[i] = g_Gp[p0*288 + i];
  __syncthreads();
  int n = blockIdx.x*128 + tid;
  float w[NJ];
  bool ok = (n < NVERT);
  if (ok) {
    const float4* wp = reinterpret_cast<const float4*>(&g_Wc[n*NJ]);
    #pragma unroll
    for (int k4 = 0; k4 < 6; ++k4) {
      float4 v = wp[k4];
      w[4*k4] = v.x; w[4*k4+1] = v.y; w[4*k4+2] = v.z; w[4*k4+3] = v.w;
    }
  }
  float ed = 0.f;
  #pragma unroll
  for (int pp = 0; pp < PC; ++pp) {
    if (!ok) break;
    int p = p0 + pp;
    float4 M0 = make_float4(0.f,0.f,0.f,0.f);
    float4 M1 = M0, M2 = M0;
    const float4* Gp4 = reinterpret_cast<const float4*>(&Gs[pp*288]);
    #pragma unroll
    for (int k = 0; k < NJ; ++k) {
      float wk = w[k];
      float4 g0 = Gp4[k*3+0], g1 = Gp4[k*3+1], g2 = Gp4[k*3+2];
      M0.x += wk*g0.x; M0.y += wk*g0.y; M0.z += wk*g0.z; M0.w += wk*g0.w;
      M1.x += wk*g1.x; M1.y += wk*g1.y; M1.z += wk*g1.z; M1.w += wk*g1.w;
      M2.x += wk*g2.x; M2.y += wk*g2.y; M2.z += wk*g2.z; M2.w += wk*g2.w;
    }
    size_t base = (size_t)p*MDIM + 3*n;
    float t0 = g_Tp[base], t1 = g_Tp[base+1], t2 = g_Tp[base+2];
    float vx = M0.x*t0 + M0.y*t1 + M0.z*t2 + M0.w;
    float vy = M1.x*t0 + M1.y*t1 + M1.z*t2 + M1.w;
    float vz = M2.x*t0 + M2.y*t1 + M2.z*t2 + M2.w;
    verts[base]   = vx;
    verts[base+1] = vy;
    verts[base+2] = vz;
    float dx = V[base]-vx, dy = V[base+1]-vy, dz = V[base+2]-vz;
    ed += dx*dx + dy*dy + dz*dz;
  }
  for (int o = 16; o > 0; o >>= 1) ed += __shfl_down_sync(0xffffffffu, ed, o);
  int lane = tid & 31, wd = tid >> 5;
  if (lane == 0) sb[wd] = ed;
  __syncthreads();
  if (tid == 0) atomicAdd(&g_acc[0], sb[0] + sb[1] + sb[2] + sb[3]);
}

// ---------------- E assembly ----------------
__global__ void finalize_kernel(const int* __restrict__ epoch_ptr, int has_epoch,
                                float* __restrict__ outE) {
  float e = has_epoch ? (float)epoch_ptr[0] : 1.f;
  float g_wi = 0.1f  *expf(-0.1f  *e);
  float g_w  = 0.002f*expf(-0.008f*e);
  float g_a  = 0.001f*expf(-0.008f*e);
  float g_k  = 0.1f  *expf(-0.008f*e);
  float ek = 0.f;
  for (int j = 0; j < 23; ++j) ek += sqrtf(g_acc[4+j]);
  outE[0] = g_acc[0] + g_wi*g_acc[1] + g_w*g_acc[2] + g_a*g_acc[3] + g_k*ek;
}

extern "C" void kernel_launch(void* const* d_in, const int* in_sizes, int n_in,
                              void* d_out, int out_size) {
  const float* V  = (const float*)d_in[0];
  const float* T  = (const float*)d_in[1];
  const float* J  = (const float*)d_in[2];
  const float* th = (const float*)d_in[3];
  const float* Wp = (const float*)d_in[4];
  const float* Wi = (const float*)d_in[5];
  const float* A  = (const float*)d_in[6];
  const float* K  = (const float*)d_in[7];
  const float* b2 = (const float*)d_in[8];
  const int*   ep = (n_in > 9) ? (const int*)d_in[9] : nullptr;

  float* out = (float*)d_out;
  int off = out_size - NP*MDIM;
  if (off < 0) off = 0;
  float* verts = out + off;

  const int GEMM_SMEM = 2*128*KS*2;        // 151552
  const int PREP_SMEM = 64*PSTR*4;         // 73984
  cudaFuncSetAttribute(gemm_mma, cudaFuncAttributeMaxDynamicSharedMemorySize, GEMM_SMEM);
  cudaFuncSetAttribute(prepB_kernel, cudaFuncAttributeMaxDynamicSharedMemorySize, PREP_SMEM);

  init_kernel<<<1, 32>>>();
  pose_kernel<<<4, 64>>>(th, J, b2);
  w_kernel<<<(NVERT + 255)/256, 256>>>(Wp, Wi, A);
  prepB_kernel<<<PBLK, 256, PREP_SMEM>>>(K, A);
  gemm_mma<<<dim3(NBT, 2), 256, GEMM_SMEM>>>(T);
  lbs_kernel<<<dim3((NVERT + 127)/128, NP/PC), 128>>>(V, verts);
  if (off > 0) finalize_kernel<<<1, 1>>>(ep, ep != nullptr ? 1 : 0, out);
}

// round 11
// speedup vs baseline: 1.6545x; 1.5111x over previous
#include <cuda_runtime.h>
#include <cuda_bf16.h>
#include <cstdint>

#define NP    200
#define NVERT 6890
#define NJ    24
#define MDIM  20670   // NVERT*3
#define KC    287     // compact K (masked rows dropped)
#define KP    288     // K padded to 18 x 16
#define KS    296     // smem A K-stride (bf16) — +8 pad, conflict-free ldmatrix
#define BPITCH 136    // smem B n-stride (bf16) — word stride 68 -> conflict-free
#define MP    256     // M padded
#define NBT   162     // N tiles of 128
#define NPAD  (NBT*128)    // 20736
#define PC    8       // poses per LBS block

__constant__ int c_PARENT[NJ] = {0,0,0,0,1,2,3,4,5,6,7,8,9,9,9,12,13,14,16,17,18,19,20,21};
__constant__ int c_LEN[NJ]    = {4,3,3,3,3,3,3,3,3,2,2,2,4,3,3,2,3,3,3,3,3,3,2,2};
__constant__ int c_NBR[NJ][4] = {
  {0,1,2,3},{0,1,4,0},{0,2,5,0},{0,3,6,0},{1,4,7,0},{2,5,8,0},{3,6,9,0},{4,7,10,0},
  {5,8,11,0},{6,9,0,0},{7,10,0,0},{8,11,0,0},{12,13,14,15},{12,13,16,0},{12,14,17,0},{12,15,0,0},
  {13,16,18,0},{14,17,19,0},{16,18,20,0},{17,19,21,0},{18,20,22,0},{19,21,23,0},{20,22,0,0},{21,23,0,0}};

// Scratch (static device globals; no runtime allocation)
__device__ __align__(16) __nv_bfloat16 g_QMbf[MP*KP];            // QM bf16, [m][k]
__device__ __align__(16) __nv_bfloat16 g_BtT[(size_t)KP*NPAD];   // B bf16, [k][n]
__device__ float g_Gp [NP*NJ*12];
__device__ float g_Wc [NVERT*NJ];
__device__ float g_Tp [NP*MDIM];
__device__ float g_acc[32];                    // 0:E_D 1:E_Wi 2:E_W 3:E_A 4..26:E_K[j]
__device__ int   g_rowjb[KP], g_rowgk[KP];     // compact-k -> (jb, global row)

__device__ __forceinline__ uint32_t smem_u32(const void* p) {
  uint32_t a;
  asm("{ .reg .u64 t; cvta.to.shared.u64 t, %1; cvt.u32.u64 %0, t; }" : "=r"(a) : "l"(p));
  return a;
}

// ---------------- init: accumulators + compact-row tables ----------------
__global__ void init_kernel() {
  if (threadIdx.x == 0) {
    int kc = 0;
    for (int jb = 0; jb < 23; ++jb) {
      int lim = 4*c_LEN[jb] + 1;
      for (int l = 0; l < lim; ++l) { g_rowjb[kc] = jb; g_rowgk[kc] = jb*17 + l; ++kc; }
    }
    for (; kc < KP; ++kc) { g_rowjb[kc] = 0; g_rowgk[kc] = 0; }
  }
  if (threadIdx.x < 32) g_acc[threadIdx.x] = 0.f;
}

// ---------------- per-pose: quats, QM bf16 rows, kinematic chain ----------------
__global__ void pose_kernel(const float* __restrict__ theta,
                            const float* __restrict__ Jin,
                            const float* __restrict__ beta2) {
  int p = blockIdx.x*blockDim.x + threadIdx.x;
  if (p >= MP) return;
  __nv_bfloat16* qrow = g_QMbf + p*KP;
  if (p >= NP) {
    for (int k = 0; k < KP; ++k) qrow[k] = __float2bfloat16(0.f);
    return;
  }
  const float* th = theta + p*72;
  const float* Jp = Jin + p*72;

  float q[NJ][4];
  float Rl[NJ][9];
  float tl[NJ][3];
  for (int k = 0; k < NJ; ++k) {
    float x = th[3*k], y = th[3*k+1], z = th[3*k+2];
    float s2 = x*x + y*y + z*z;
    float aq = sqrtf(fmaxf(s2, 1e-16f));
    float sh = sinf(0.5f*aq);
    float iq = 1.f/aq;
    q[k][0] = x*iq*sh; q[k][1] = y*iq*sh; q[k][2] = z*iq*sh;
    q[k][3] = cosf(0.5f*aq) - 1.f;
    float a = fmaxf(sqrtf(s2), 1e-8f);
    float ia = 1.f/a;
    float nx = x*ia, ny = y*ia, nz = z*ia;
    float c = cosf(a), s = sinf(a), t1 = 1.f - c;
    Rl[k][0] = c + t1*nx*nx;    Rl[k][1] = t1*nx*ny - s*nz; Rl[k][2] = t1*nx*nz + s*ny;
    Rl[k][3] = t1*nx*ny + s*nz; Rl[k][4] = c + t1*ny*ny;    Rl[k][5] = t1*ny*nz - s*nx;
    Rl[k][6] = t1*nx*nz - s*ny; Rl[k][7] = t1*ny*nz + s*nx; Rl[k][8] = c + t1*nz*nz;
    if (k == 0) { tl[k][0]=Jp[0]; tl[k][1]=Jp[1]; tl[k][2]=Jp[2]; }
    else {
      int par = c_PARENT[k];
      tl[k][0] = Jp[3*k]   - Jp[3*par];
      tl[k][1] = Jp[3*k+1] - Jp[3*par+1];
      tl[k][2] = Jp[3*k+2] - Jp[3*par+2];
    }
  }
  float Rw[NJ][9], tw[NJ][3];
  for (int i = 0; i < 9; ++i) Rw[0][i] = Rl[0][i];
  for (int i = 0; i < 3; ++i) tw[0][i] = tl[0][i];
  for (int k = 1; k < NJ; ++k) {
    int par = c_PARENT[k];
    for (int i = 0; i < 3; ++i) {
      for (int j = 0; j < 3; ++j) {
        Rw[k][i*3+j] = Rw[par][i*3+0]*Rl[k][0+j] + Rw[par][i*3+1]*Rl[k][3+j] + Rw[par][i*3+2]*Rl[k][6+j];
      }
      tw[k][i] = Rw[par][i*3+0]*tl[k][0] + Rw[par][i*3+1]*tl[k][1] + Rw[par][i*3+2]*tl[k][2] + tw[par][i];
    }
  }
  for (int k = 0; k < NJ; ++k) {
    float jx = Jp[3*k], jy = Jp[3*k+1], jz = Jp[3*k+2];
    for (int i = 0; i < 3; ++i) {
      float off = Rw[k][i*3]*jx + Rw[k][i*3+1]*jy + Rw[k][i*3+2]*jz;
      g_Gp[p*288 + k*12 + i*4 + 0] = Rw[k][i*3+0];
      g_Gp[p*288 + k*12 + i*4 + 1] = Rw[k][i*3+1];
      g_Gp[p*288 + k*12 + i*4 + 2] = Rw[k][i*3+2];
      g_Gp[p*288 + k*12 + i*4 + 3] = tw[k][i] - off;
    }
  }
  // compact qm row -> bf16 (masked l positions dropped entirely)
  float b2 = beta2[0];
  int kc = 0;
  for (int j = 0; j < 23; ++j) {
    int jj = j + 1;
    int lim  = 4*c_LEN[j] + 1;
    int bpos = 4*c_LEN[jj];
    for (int l = 0; l < lim; ++l) {
      float v = 0.f;
      if (l < 16) {
        int g = l >> 2, cc = l & 3;
        if (g < c_LEN[jj]) v = q[c_NBR[jj][g]][cc];
      }
      if (l == bpos) v += b2;
      qrow[kc++] = __float2bfloat16(v);
    }
  }
  for (; kc < KP; ++kc) qrow[kc] = __float2bfloat16(0.f);
}

// ---------------- weights: W_change, E_Wi, E_W, E_A ----------------
__global__ void w_kernel(const float* __restrict__ Wp, const float* __restrict__ Wi,
                         const float* __restrict__ A) {
  __shared__ float sb0[8], sb1[8], sb2[8];
  int n = blockIdx.x*blockDim.x + threadIdx.x;
  float ewi = 0.f, ew = 0.f, ea = 0.f;
  if (n < NVERT) {
    float w[NJ]; float s = 0.f;
    #pragma unroll
    for (int k = 0; k < NJ; ++k) { w[k] = fmaxf(Wp[n*NJ+k], 0.f); s += w[k]; }
    float inv = 1.f/(s + 1e-8f);
    #pragma unroll
    for (int k = 0; k < NJ; ++k) {
      float wc = w[k]*inv;
      g_Wc[n*NJ + k] = wc;
      float d = wc - Wi[n*NJ+k];
      ewi += d*d;
      ew  += fabsf(wc);
    }
    for (int j = 0; j < 23; ++j) ea += fabsf(A[j*NVERT + n]);
  }
  for (int o = 16; o > 0; o >>= 1) {
    ewi += __shfl_down_sync(0xffffffffu, ewi, o);
    ew  += __shfl_down_sync(0xffffffffu, ew,  o);
    ea  += __shfl_down_sync(0xffffffffu, ea,  o);
  }
  int lane = threadIdx.x & 31, wid = threadIdx.x >> 5;
  if (lane == 0) { sb0[wid]=ewi; sb1[wid]=ew; sb2[wid]=ea; }
  __syncthreads();
  if (wid == 0) {
    ewi = (lane < 8) ? sb0[lane] : 0.f;
    ew  = (lane < 8) ? sb1[lane] : 0.f;
    ea  = (lane < 8) ? sb2[lane] : 0.f;
    for (int o = 4; o > 0; o >>= 1) {
      ewi += __shfl_down_sync(0xffffffffu, ewi, o);
      ew  += __shfl_down_sync(0xffffffffu, ew,  o);
      ea  += __shfl_down_sync(0xffffffffu, ea,  o);
    }
    if (lane == 0) {
      atomicAdd(&g_acc[1], ewi);
      atomicAdd(&g_acc[2], ew);
      atomicAdd(&g_acc[3], ea);
    }
  }
}

// ---------------- scaleK: g_BtT[k][n] = bf16(relu(A[jb,n/3]) * K[gk][n]), + E_K ----
// Pure streaming map, no transpose, no branch between loads. One k-row per blockIdx.y.
__global__ void __launch_bounds__(256) scaleK_kernel(const float* __restrict__ K,
                                                     const float* __restrict__ A) {
  __shared__ float sb[8];
  int k = blockIdx.y;
  int jb = g_rowjb[k], gk = g_rowgk[k];
  bool live = (k < KC);
  int tid = threadIdx.x;
  int n0 = blockIdx.x * 2048;
  const float* Krow = K + (size_t)gk*MDIM;
  const float* Aj = A + jb*NVERT;
  uint32_t* drow = (uint32_t*)(g_BtT + (size_t)k*NPAD);
  float ssq = 0.f;
  #pragma unroll
  for (int u = 0; u < 4; ++u) {
    int n = n0 + (tid + u*256)*2;
    if (n < NPAD) {
      float v0 = 0.f, v1 = 0.f, w0 = 0.f, w1 = 0.f;
      if (live && n < MDIM) {                      // n even, MDIM even -> pair in range
        float2 kv = *(const float2*)(Krow + n);
        v0 = kv.x; v1 = kv.y;
        w0 = fmaxf(__ldg(Aj + n/3), 0.f);
        w1 = fmaxf(__ldg(Aj + (n+1)/3), 0.f);
        ssq += v0*v0 + v1*v1;
      }
      __nv_bfloat162 h = __floats2bfloat162_rn(v0*w0, v1*w1);
      drow[n >> 1] = *(uint32_t*)&h;
    }
  }
  // block reduce ssq -> one atomic per block
  for (int o = 16; o > 0; o >>= 1) ssq += __shfl_down_sync(0xffffffffu, ssq, o);
  int lane = tid & 31, wid = tid >> 5;
  if (lane == 0) sb[wid] = ssq;
  __syncthreads();
  if (wid == 0) {
    ssq = (lane < 8) ? sb[lane] : 0.f;
    for (int o = 4; o > 0; o >>= 1) ssq += __shfl_down_sync(0xffffffffu, ssq, o);
    if (lane == 0 && live && ssq != 0.f) atomicAdd(&g_acc[4 + jb], ssq);
  }
}

// ---------------- tensor-core GEMM via mma.sync bf16 (valid on plain sm_103) ----
// CTA 256 thr = 8 warps (4m x 2n), warp tile 32x64, CTA tile 128x128, full K=288 in smem.
// A: [m][k] ldmatrix non-trans; B: [k][n] ldmatrix.trans.
__global__ void __launch_bounds__(256) gemm_mma(const float* __restrict__ T) {
  extern __shared__ char smem[];
  char* sA = smem;                       // [128][KS] bf16 = 75776 B
  char* sB = smem + 128*KS*2;            // [KP][BPITCH] bf16 = 78336 B
  int tid = threadIdx.x;
  int m0 = blockIdx.y*128, n0 = blockIdx.x*128;

  // fill A tile (rows m0..m0+127); row stride gmem 288 bf16 = 36 uint4
  {
    const uint4* Ag = (const uint4*)g_QMbf + (size_t)m0*36;
    for (int i = tid; i < 128*36; i += 256) {
      int r = i/36, c = i - r*36;
      uint4 v = Ag[(size_t)r*36 + c];
      *(uint4*)(sA + (r*KS + c*8)*2) = v;
    }
  }
  // fill B tile: rows k 0..287, cols n0..n0+127 (16 uint4 per row)
  {
    for (int i = tid; i < KP*16; i += 256) {
      int r = i >> 4, c = i & 15;
      uint4 v = *(const uint4*)(g_BtT + (size_t)r*NPAD + n0 + c*8);
      *(uint4*)(sB + (r*BPITCH + c*8)*2) = v;
    }
  }
  __syncthreads();

  uint32_t sAu = smem_u32(sA), sBu = smem_u32(sB);
  int warp = tid >> 5, lane = tid & 31;
  int wm = (warp >> 1) * 32;   // 0,32,64,96
  int wn = (warp & 1) * 64;    // 0,64

  float acc[2][8][4];
  #pragma unroll
  for (int mi = 0; mi < 2; ++mi)
    #pragma unroll
    for (int ni = 0; ni < 8; ++ni)
      #pragma unroll
      for (int r = 0; r < 4; ++r) acc[mi][ni][r] = 0.f;

  // ldmatrix lane address components
  int la_row = wm + (lane & 7) + ((lane >> 3) & 1) * 8;
  int la_k8  = (lane >> 4) * 8;
  int lb_k   = lane & 15;              // k row within k16 step
  int lb_n8  = (lane >> 4) * 8;        // n sub-tile select

  for (int ks = 0; ks < KP/16; ++ks) {
    int k0 = ks*16;
    uint32_t a[2][4];
    #pragma unroll
    for (int mi = 0; mi < 2; ++mi) {
      uint32_t ad = sAu + (uint32_t)(((la_row + mi*16)*KS + k0 + la_k8) * 2);
      asm volatile("ldmatrix.sync.aligned.m8n8.x4.shared.b16 {%0,%1,%2,%3}, [%4];"
        : "=r"(a[mi][0]), "=r"(a[mi][1]), "=r"(a[mi][2]), "=r"(a[mi][3]) : "r"(ad));
    }
    uint32_t b[8][2];
    #pragma unroll
    for (int bi = 0; bi < 4; ++bi) {
      uint32_t ad = sBu + (uint32_t)(((k0 + lb_k)*BPITCH + wn + bi*16 + lb_n8) * 2);
      uint32_t r0, r1, r2, r3;
      asm volatile("ldmatrix.sync.aligned.m8n8.x4.trans.shared.b16 {%0,%1,%2,%3}, [%4];"
        : "=r"(r0), "=r"(r1), "=r"(r2), "=r"(r3) : "r"(ad));
      b[2*bi][0] = r0;   b[2*bi][1] = r1;
      b[2*bi+1][0] = r2; b[2*bi+1][1] = r3;
    }
    #pragma unroll
    for (int mi = 0; mi < 2; ++mi)
      #pragma unroll
      for (int ni = 0; ni < 8; ++ni) {
        asm volatile(
          "mma.sync.aligned.m16n8k16.row.col.f32.bf16.bf16.f32 "
          "{%0,%1,%2,%3}, {%4,%5,%6,%7}, {%8,%9}, {%0,%1,%2,%3};"
          : "+f"(acc[mi][ni][0]), "+f"(acc[mi][ni][1]),
            "+f"(acc[mi][ni][2]), "+f"(acc[mi][ni][3])
          : "r"(a[mi][0]), "r"(a[mi][1]), "r"(a[mi][2]), "r"(a[mi][3]),
            "r"(b[ni][0]), "r"(b[ni][1]));
      }
  }

  // epilogue: += T, store to g_Tp
  int rbase = lane >> 2, cbase = (lane & 3) * 2;
  #pragma unroll
  for (int mi = 0; mi < 2; ++mi) {
    #pragma unroll
    for (int ni = 0; ni < 8; ++ni) {
      int row = m0 + wm + mi*16 + rbase;
      int col = n0 + wn + ni*8 + cbase;
      if (col + 1 < MDIM) {
        if (row < NP) {
          size_t o = (size_t)row*MDIM + col;
          float2 t = *(const float2*)(T + o);
          float2 w; w.x = acc[mi][ni][0] + t.x; w.y = acc[mi][ni][1] + t.y;
          *(float2*)(g_Tp + o) = w;
        }
        int row2 = row + 8;
        if (row2 < NP) {
          size_t o = (size_t)row2*MDIM + col;
          float2 t = *(const float2*)(T + o);
          float2 w; w.x = acc[mi][ni][2] + t.x; w.y = acc[mi][ni][3] + t.y;
          *(float2*)(g_Tp + o) = w;
        }
      }
    }
  }
}

// ---------------- LBS blend + verts + E_D ----------------
__global__ void __launch_bounds__(128) lbs_kernel(const float* __restrict__ V,
                                                  float* __restrict__ verts) {
  __shared__ __align__(16) float Gs[PC*288];
  __shared__ float sb[4];
  int tid = threadIdx.x;
  int p0 = blockIdx.y*PC;
  for (int i = tid; i < PC*288; i += 128) Gs[i] = g_Gp[p0*288 + i];
  __syncthreads();
  int n = blockIdx.x*128 + tid;
  float w[NJ];
  bool ok = (n < NVERT);
  if (ok) {
    const float4* wp = reinterpret_cast<const float4*>(&g_Wc[n*NJ]);
    #pragma unroll
    for (int k4 = 0; k4 < 6; ++k4) {
      float4 v = wp[k4];
      w[4*k4] = v.x; w[4*k4+1] = v.y; w[4*k4+2] = v.z; w[4*k4+3] = v.w;
    }
  }
  float ed = 0.f;
  #pragma unroll
  for (int pp = 0; pp < PC; ++pp) {
    if (!ok) break;
    int p = p0 + pp;
    float4 M0 = make_float4(0.f,0.f,0.f,0.f);
    float4 M1 = M0, M2 = M0;
    const float4* Gp4 = reinterpret_cast<const float4*>(&Gs[pp*288]);
    #pragma unroll
    for (int k = 0; k < NJ; ++k) {
      float wk = w[k];
      float4 g0 = Gp4[k*3+0], g1 = Gp4[k*3+1], g2 = Gp4[k*3+2];
      M0.x += wk*g0.x; M0.y += wk*g0.y; M0.z += wk*g0.z; M0.w += wk*g0.w;
      M1.x += wk*g1.x; M1.y += wk*g1.y; M1.z += wk*g1.z; M1.w += wk*g1.w;
      M2.x += wk*g2.x; M2.y += wk*g2.y; M2.z += wk*g2.z; M2.w += wk*g2.w;
    }
    size_t base = (size_t)p*MDIM + 3*n;
    float t0 = g_Tp[base], t1 = g_Tp[base+1], t2 = g_Tp[base+2];
    float vx = M0.x*t0 + M0.y*t1 + M0.z*t2 + M0.w;
    float vy = M1.x*t0 + M1.y*t1 + M1.z*t2 + M1.w;
    float vz = M2.x*t0 + M2.y*t1 + M2.z*t2 + M2.w;
    verts[base]   = vx;
    verts[base+1] = vy;
    verts[base+2] = vz;
    float dx = V[base]-vx, dy = V[base+1]-vy, dz = V[base+2]-vz;
    ed += dx*dx + dy*dy + dz*dz;
  }
  for (int o = 16; o > 0; o >>= 1) ed += __shfl_down_sync(0xffffffffu, ed, o);
  int lane = tid & 31, wd = tid >> 5;
  if (lane == 0) sb[wd] = ed;
  __syncthreads();
  if (tid == 0) atomicAdd(&g_acc[0], sb[0] + sb[1] + sb[2] + sb[3]);
}

// ---------------- E assembly ----------------
__global__ void finalize_kernel(const int* __restrict__ epoch_ptr, int has_epoch,
                                float* __restrict__ outE) {
  float e = has_epoch ? (float)epoch_ptr[0] : 1.f;
  float g_wi = 0.1f  *expf(-0.1f  *e);
  float g_w  = 0.002f*expf(-0.008f*e);
  float g_a  = 0.001f*expf(-0.008f*e);
  float g_k  = 0.1f  *expf(-0.008f*e);
  float ek = 0.f;
  for (int j = 0; j < 23; ++j) ek += sqrtf(g_acc[4+j]);
  outE[0] = g_acc[0] + g_wi*g_acc[1] + g_w*g_acc[2] + g_a*g_acc[3] + g_k*ek;
}

extern "C" void kernel_launch(void* const* d_in, const int* in_sizes, int n_in,
                              void* d_out, int out_size) {
  const float* V  = (const float*)d_in[0];
  const float* T  = (const float*)d_in[1];
  const float* J  = (const float*)d_in[2];
  const float* th = (const float*)d_in[3];
  const float* Wp = (const float*)d_in[4];
  const float* Wi = (const float*)d_in[5];
  const float* A  = (const float*)d_in[6];
  const float* K  = (const float*)d_in[7];
  const float* b2 = (const float*)d_in[8];
  const int*   ep = (n_in > 9) ? (const int*)d_in[9] : nullptr;

  float* out = (float*)d_out;
  int off = out_size - NP*MDIM;
  if (off < 0) off = 0;
  float* verts = out + off;

  const int GEMM_SMEM = 128*KS*2 + KP*BPITCH*2;   // 75776 + 78336 = 154112
  cudaFuncSetAttribute(gemm_mma, cudaFuncAttributeMaxDynamicSharedMemorySize, GEMM_SMEM);

  init_kernel<<<1, 32>>>();
  pose_kernel<<<4, 64>>>(th, J, b2);
  w_kernel<<<(NVERT + 255)/256, 256>>>(Wp, Wi, A);
  scaleK_kernel<<<dim3((NPAD + 2047)/2048, KP), 256>>>(K, A);
  gemm_mma<<<dim3(NBT, 2), 256, GEMM_SMEM>>>(T);
  lbs_kernel<<<dim3((NVERT + 127)/128, NP/PC), 128>>>(V, verts);
  if (off > 0) finalize_kernel<<<1, 1>>>(ep, ep != nullptr ? 1 : 0, out);
}